// round 1
// baseline (speedup 1.0000x reference)
#include <cuda_runtime.h>
#include <cuda_bf16.h>
#include <cstdint>

// Problem constants
#define SB   4
#define SS   2048
#define SEQ  2046     // S - 2
#define NH   12
#define ND   64
#define TJ   64       // j-tile per block
#define TL   64       // l-chunk

// ---------------- packed fp32x2 helpers (PTX-only path, 2x fma throughput) ---
__device__ __forceinline__ unsigned long long pack2(float x, float y) {
    unsigned long long r;
    asm("mov.b64 %0, {%1, %2};" : "=l"(r) : "f"(x), "f"(y));
    return r;
}
__device__ __forceinline__ unsigned long long ffma2(unsigned long long a,
                                                    unsigned long long b,
                                                    unsigned long long c) {
    unsigned long long d;
    asm("fma.rn.f32x2 %0, %1, %2, %3;" : "=l"(d) : "l"(a), "l"(b), "l"(c));
    return d;
}
__device__ __forceinline__ void unpack2(unsigned long long p, float& x, float& y) {
    asm("mov.b64 {%0, %1}, %2;" : "=f"(x), "=f"(y) : "l"(p));
}

// ---------------------------------------------------------------------------
// pbv[n,j,h,d] = sum_{l=1..SEQ} w[h,|l-j|] * v[n,l,h,d]   (j in 1..SEQ)
// Block: one (n,h), one 64-wide j tile, full D=64.
// 256 threads: jj = t&63, dg = t>>6 covers d in [dg*16, dg*16+16).
// ---------------------------------------------------------------------------
__global__ __launch_bounds__(256) void pbv_kernel(const float* __restrict__ v,
                                                  const float* __restrict__ w,
                                                  float* __restrict__ out) {
    const int nh = blockIdx.y;
    const int n = nh / NH, h = nh % NH;
    const int j0 = 1 + blockIdx.x * TJ;

    __shared__ float vs[TL * ND];     // 16 KB V tile
    __shared__ float ws[TJ + TL];     // 128 floats, delta window

    const int t  = threadIdx.x;
    const int jj = t & 63;
    const int dg = t >> 6;            // 0..3
    const int dbase = dg * 16;

    const float* vbase = v + ((size_t)n * SS * NH + h) * ND;   // + l*NH*ND + d
    const float* wrow  = w + (size_t)h * SS;

    unsigned long long acc[8];
#pragma unroll
    for (int i = 0; i < 8; i++) acc[i] = pack2(0.f, 0.f);

    for (int c = 0; c < SS / TL; c++) {
        const int ll0 = 1 + c * TL;

        __syncthreads();   // protect smem from previous iteration's readers

        // ---- stage V tile (zero-fill rows past SEQ so inner loop is branch-free)
#pragma unroll
        for (int q = 0; q < 4; q++) {
            int fi  = t + q * 256;        // float4 index 0..1023
            int row = fi >> 4;            // 0..63
            int col = (fi & 15) * 4;
            int l   = ll0 + row;
            float4 val = make_float4(0.f, 0.f, 0.f, 0.f);
            if (l <= SEQ)
                val = *(const float4*)(vbase + (size_t)l * (NH * ND) + col);
            *(float4*)(vs + row * ND + col) = val;
        }
        // ---- stage w window: ws[u] = w[h, |ll0 - j0 + u - 63|], u in [0,126]
        if (t < 127) {
            int delta = ll0 - j0 + t - 63;
            int a = delta < 0 ? -delta : delta;   // always <= 2047 for u<=126
            ws[t] = wrow[a];
        }
        __syncthreads();

#pragma unroll 8
        for (int r = 0; r < TL; r++) {
            float wv = ws[r - jj + 63];                 // conflict-free
            unsigned long long wp = pack2(wv, wv);
            const float4* vrow = (const float4*)(vs + r * ND + dbase); // broadcast
            float4 a0 = vrow[0], a1 = vrow[1], a2 = vrow[2], a3 = vrow[3];
            acc[0] = ffma2(pack2(a0.x, a0.y), wp, acc[0]);
            acc[1] = ffma2(pack2(a0.z, a0.w), wp, acc[1]);
            acc[2] = ffma2(pack2(a1.x, a1.y), wp, acc[2]);
            acc[3] = ffma2(pack2(a1.z, a1.w), wp, acc[3]);
            acc[4] = ffma2(pack2(a2.x, a2.y), wp, acc[4]);
            acc[5] = ffma2(pack2(a2.z, a2.w), wp, acc[5]);
            acc[6] = ffma2(pack2(a3.x, a3.y), wp, acc[6]);
            acc[7] = ffma2(pack2(a3.z, a3.w), wp, acc[7]);
        }
    }

    const int j = j0 + jj;
    if (j <= SEQ) {
        float* o = out + ((size_t)(n * SS + j) * NH + h) * ND + dbase;
#pragma unroll
        for (int i = 0; i < 4; i++) {
            float4 val;
            unpack2(acc[2 * i],     val.x, val.y);
            unpack2(acc[2 * i + 1], val.z, val.w);
            *(float4*)(o + i * 4) = val;
        }
    }
}

// ---------------------------------------------------------------------------
// z_pb[l,h] = P[l-1] + P[SEQ-l] - w[h,0] for l in 1..SEQ, else 0.
// One block per head; Hillis-Steele inclusive scan over 2048 (padded) entries.
// ---------------------------------------------------------------------------
__global__ __launch_bounds__(1024) void z_kernel(const float* __restrict__ w,
                                                 float* __restrict__ outz) {
    const int h = blockIdx.x;
    __shared__ float buf[2][SS];

    for (int i = threadIdx.x; i < SS; i += 1024)
        buf[0][i] = (i < SEQ) ? w[(size_t)h * SS + i] : 0.f;
    __syncthreads();

    int src = 0;
    for (int off = 1; off < SS; off <<= 1) {
        for (int i = threadIdx.x; i < SS; i += 1024) {
            float val = buf[src][i];
            if (i >= off) val += buf[src][i - off];
            buf[src ^ 1][i] = val;
        }
        src ^= 1;
        __syncthreads();
    }

    const float w0 = buf[src][0];   // P[0] == w[h,0]
    for (int l = threadIdx.x; l < SS; l += 1024) {
        float zv = 0.f;
        if (l >= 1 && l <= SEQ)
            zv = buf[src][l - 1] + buf[src][SEQ - l] - w0;
        outz[(size_t)l * NH + h] = zv;
    }
}

// ---------------------------------------------------------------------------
// Zero the padded pbv rows j=0 and j=2047 (d_out is poisoned to 0xAA).
// 8 segments of NH*ND = 768 floats each -> 6144 elements.
// ---------------------------------------------------------------------------
__global__ void border_kernel(float* __restrict__ out) {
    int g = blockIdx.x * blockDim.x + threadIdx.x;
    if (g >= 8 * NH * ND) return;
    int seg = g / (NH * ND);
    int off = g % (NH * ND);
    int n = seg >> 1;
    int j = (seg & 1) ? (SS - 1) : 0;
    out[((size_t)(n * SS + j) * NH * ND) + off] = 0.f;
}

// ---------------------------------------------------------------------------
extern "C" void kernel_launch(void* const* d_in, const int* in_sizes, int n_in,
                              void* d_out, int out_size) {
    const float* a0 = (const float*)d_in[0];
    const float* a1 = (const float*)d_in[1];
    // v is the big tensor (6.29M elems), w is 24576. Defensive identify.
    const float* v = a0;
    const float* w = a1;
    if (n_in >= 2 && in_sizes[0] < in_sizes[1]) { v = a1; w = a0; }

    float* out  = (float*)d_out;
    float* outz = out + (size_t)SB * SS * NH * ND;

    dim3 grid(SS / TL, SB * NH);       // 32 x 48 = 1536 blocks
    pbv_kernel<<<grid, 256>>>(v, w, out);
    z_kernel<<<NH, 1024>>>(w, outz);
    border_kernel<<<6, 1024>>>(out);
}

// round 4
// speedup vs baseline: 2.5509x; 2.5509x over previous
#include <cuda_runtime.h>
#include <cuda_bf16.h>
#include <cstdint>

// ---------------- problem constants ----------------
#define SB   4
#define SS   2048
#define SEQ  2046
#define NH   12
#define ND   64
#define ROWSTRIDE (NH*ND)        // 768 floats between consecutive l in v

// ---------------- GEMM tiling ----------------
#define TM    128                // j rows per CTA
#define TN    128                // c cols per CTA (2 n * 64 d)
#define KC    32                 // l per chunk
#define NCHUNK (SS / KC)         // 64
#define ASTRIDE 136              // floats per k-row (128 + 8 pad): bank = k*8+j
#define THREADS 256

__device__ __forceinline__ float tf32_rn(float x) {
    uint32_t u;
    asm("cvt.rna.tf32.f32 %0, %1;" : "=r"(u) : "f"(x));
    return __uint_as_float(u);
}

__device__ __forceinline__ void mma_tf32(float* d, const uint32_t* a,
                                         const uint32_t* b) {
    asm volatile(
        "mma.sync.aligned.m16n8k8.row.col.f32.tf32.tf32.f32 "
        "{%0,%1,%2,%3}, {%4,%5,%6,%7}, {%8,%9}, {%0,%1,%2,%3};"
        : "+f"(d[0]), "+f"(d[1]), "+f"(d[2]), "+f"(d[3])
        : "r"(a[0]), "r"(a[1]), "r"(a[2]), "r"(a[3]), "r"(b[0]), "r"(b[1]));
}

// ---------------------------------------------------------------------------
// pbv[n,j,h,d] = sum_l w[h,|l-j|] * v[n,l,h,d], as a per-head Toeplitz GEMM.
// grid (16 j-tiles, 2 c-halves, 12 heads); CTA 128x128, 8 warps of 64x32.
// ---------------------------------------------------------------------------
__global__ __launch_bounds__(THREADS, 2) void pbv_mma(const float* __restrict__ v,
                                                      const float* __restrict__ w,
                                                      float* __restrict__ out) {
    __shared__ float    wsf[SS];                 // 8 KB, tf32-rounded w row
    __shared__ uint32_t As[KC][ASTRIDE];         // Toeplitz tile [k][j]  17.4 KB
    __shared__ uint32_t Bs[KC][ASTRIDE];         // V tile        [k][c]  17.4 KB

    const int t   = threadIdx.x;
    const int wid = t >> 5, lane = t & 31;
    const int g   = lane >> 2, t4 = lane & 3;
    const int wm  = wid >> 2;                    // 0..1 -> 64-row slab
    const int wn  = wid & 3;                     // 0..3 -> 32-col slab

    const int jt = blockIdx.x, ch = blockIdx.y, h = blockIdx.z;
    const int j0 = jt * TM;                      // rows j0..j0+127 (0..2047)
    const int c0 = ch * TN;                      // cols c0..c0+127 (of 256)

    // stage w row, pre-rounded to tf32
    {
        const float* wrow = w + (size_t)h * SS;
        for (int i = t; i < SS; i += THREADS) wsf[i] = tf32_rn(wrow[i]);
    }

    const float* vbase = v + h * ND;             // + (n*SS + l)*ROWSTRIDE + d

    float acc[4][4][4];
#pragma unroll
    for (int mi = 0; mi < 4; mi++)
#pragma unroll
        for (int ni = 0; ni < 4; ni++)
#pragma unroll
            for (int r = 0; r < 4; r++) acc[mi][ni][r] = 0.f;

    for (int c = 0; c < NCHUNK; c++) {
        const int k0 = c * KC;
        __syncthreads();                         // prior chunk's readers done

        // ---- stage A: As[k][j] = (valid l) ? w[h,|l-(j0+j)|] : 0
#pragma unroll
        for (int i = 0; i < 16; i++) {
            int e = t + i * THREADS;             // 0..4095
            int k = e >> 7, j = e & 127;
            int l = k0 + k;
            int delta = l - (j0 + j);
            int ad = delta < 0 ? -delta : delta;
            float val = (l >= 1 && l <= SEQ) ? wsf[ad] : 0.f;
            As[k][j] = __float_as_uint(val);
        }
        // ---- stage B: Bs[k][cc] = tf32(v[n, l, h, d]),  c = c0+cc -> (n,d)
#pragma unroll
        for (int q = 0; q < 4; q++) {
            int fi = t + q * THREADS;            // float4 slot 0..1023
            int k  = fi >> 5;
            int c4 = fi & 31;
            int cc = c0 + c4 * 4;
            int n  = cc >> 6, d = cc & 63;
            const float4 vv = *(const float4*)(vbase +
                ((size_t)n * SS + (k0 + k)) * ROWSTRIDE + d);
            uint4 rv;
            rv.x = __float_as_uint(tf32_rn(vv.x));
            rv.y = __float_as_uint(tf32_rn(vv.y));
            rv.z = __float_as_uint(tf32_rn(vv.z));
            rv.w = __float_as_uint(tf32_rn(vv.w));
            *(uint4*)&Bs[k][c4 * 4] = rv;
        }
        __syncthreads();

        // ---- compute: 4 k-steps of 8, 4x4 mma tiles per warp
#pragma unroll
        for (int ks = 0; ks < 4; ks++) {
            const int kb = ks * 8;
            uint32_t a[4][4], b[4][2];
#pragma unroll
            for (int mi = 0; mi < 4; mi++) {
                const int j = wm * 64 + mi * 16 + g;
                a[mi][0] = As[kb + t4][j];
                a[mi][1] = As[kb + t4][j + 8];
                a[mi][2] = As[kb + t4 + 4][j];
                a[mi][3] = As[kb + t4 + 4][j + 8];
            }
#pragma unroll
            for (int ni = 0; ni < 4; ni++) {
                const int cc = wn * 32 + ni * 8 + g;
                b[ni][0] = Bs[kb + t4][cc];
                b[ni][1] = Bs[kb + t4 + 4][cc];
            }
#pragma unroll
            for (int mi = 0; mi < 4; mi++)
#pragma unroll
                for (int ni = 0; ni < 4; ni++)
                    mma_tf32(acc[mi][ni], a[mi], b[ni]);
        }
    }

    // ---- epilogue: acc -> out[n, j, h, d]
#pragma unroll
    for (int mi = 0; mi < 4; mi++) {
        const int r0 = j0 + wm * 64 + mi * 16 + g;
#pragma unroll
        for (int ni = 0; ni < 4; ni++) {
            const int cc = c0 + wn * 32 + ni * 8 + 2 * t4;
            const int n = cc >> 6, d = cc & 63;
            float* o = out + (((size_t)n * SS) * NH + h) * ND + d;
            if (r0 >= 1 && r0 <= SEQ) {
                float2 s = make_float2(acc[mi][ni][0], acc[mi][ni][1]);
                *(float2*)(o + (size_t)r0 * NH * ND) = s;
            }
            const int r1 = r0 + 8;
            if (r1 >= 1 && r1 <= SEQ) {
                float2 s = make_float2(acc[mi][ni][2], acc[mi][ni][3]);
                *(float2*)(o + (size_t)r1 * NH * ND) = s;
            }
        }
    }
}

// ---------------------------------------------------------------------------
// z_pb[l,h] = P[l-1] + P[SEQ-l] - w[h,0]; Hillis-Steele scan per head
// ---------------------------------------------------------------------------
__global__ __launch_bounds__(1024) void z_kernel(const float* __restrict__ w,
                                                 float* __restrict__ outz) {
    const int h = blockIdx.x;
    __shared__ float buf[2][SS];
    for (int i = threadIdx.x; i < SS; i += 1024)
        buf[0][i] = (i < SEQ) ? w[(size_t)h * SS + i] : 0.f;
    __syncthreads();
    int src = 0;
    for (int off = 1; off < SS; off <<= 1) {
        for (int i = threadIdx.x; i < SS; i += 1024) {
            float val = buf[src][i];
            if (i >= off) val += buf[src][i - off];
            buf[src ^ 1][i] = val;
        }
        src ^= 1;
        __syncthreads();
    }
    const float w0 = buf[src][0];
    for (int l = threadIdx.x; l < SS; l += 1024) {
        float zv = 0.f;
        if (l >= 1 && l <= SEQ)
            zv = buf[src][l - 1] + buf[src][SEQ - l] - w0;
        outz[(size_t)l * NH + h] = zv;
    }
}

// zero pbv border rows j=0 and j=2047 (d_out poisoned)
__global__ void border_kernel(float* __restrict__ out) {
    int g = blockIdx.x * blockDim.x + threadIdx.x;
    if (g >= 8 * NH * ND) return;
    int seg = g / (NH * ND);
    int off = g % (NH * ND);
    int n = seg >> 1;
    int j = (seg & 1) ? (SS - 1) : 0;
    out[((size_t)(n * SS + j) * NH * ND) + off] = 0.f;
}

// ---------------------------------------------------------------------------
extern "C" void kernel_launch(void* const* d_in, const int* in_sizes, int n_in,
                              void* d_out, int out_size) {
    const float* a0 = (const float*)d_in[0];
    const float* a1 = (const float*)d_in[1];
    const float* v = a0;
    const float* w = a1;
    if (n_in >= 2 && in_sizes[0] < in_sizes[1]) { v = a1; w = a0; }

    float* out  = (float*)d_out;
    float* outz = out + (size_t)SB * SS * NH * ND;

    dim3 grid(SS / TM, 2, NH);               // 16 x 2 x 12 = 384 CTAs
    pbv_mma<<<grid, THREADS>>>(v, w, out);
    z_kernel<<<NH, 1024>>>(w, outz);
    border_kernel<<<6, 1024>>>(out);
}

// round 5
// speedup vs baseline: 4.1020x; 1.6081x over previous
#include <cuda_runtime.h>
#include <cuda_bf16.h>
#include <cstdint>

// ---------------- problem constants ----------------
#define SB   4
#define SS   2048
#define SEQ  2046
#define NH   12
#define ND   64
#define ROWSTRIDE (NH*ND)        // 768 floats between consecutive l in v
#define NV   (SB*SS*NH*ND)       // 6291456 elements of v

// ---------------- GEMM tiling ----------------
#define TM    128                // j rows per CTA
#define TN    128                // c cols per CTA (2 n * 64 d)
#define KC    32                 // l per chunk
#define NCHUNK (SS / KC)         // 64
#define ASTRIDE 136              // floats per k-row (128 + 8 pad)
#define TILEU  (KC*ASTRIDE)      // uint32 per tile buffer (4352)
#define DYN_BYTES (4*TILEU*4)    // 69632 B: As0,As1,Bs0,Bs1
#define THREADS 256

// tf32-prerounded copy of v (scratch; device globals are the allowed scratch)
__device__ float vt_buf[NV];

__device__ __forceinline__ float tf32_rn(float x) {
    uint32_t u;
    asm("cvt.rna.tf32.f32 %0, %1;" : "=r"(u) : "f"(x));
    return __uint_as_float(u);
}
__device__ __forceinline__ uint32_t smem_u32(const void* p) {
    uint32_t a;
    asm("{ .reg .u64 t; cvta.to.shared.u64 t, %1; cvt.u32.u64 %0, t; }"
        : "=r"(a) : "l"(p));
    return a;
}
__device__ __forceinline__ void cp_async16(uint32_t dst, const void* src) {
    asm volatile("cp.async.ca.shared.global [%0], [%1], 16;"
                 :: "r"(dst), "l"(src) : "memory");
}
#define CP_COMMIT() asm volatile("cp.async.commit_group;" ::: "memory")
#define CP_WAIT0()  asm volatile("cp.async.wait_group 0;" ::: "memory")

__device__ __forceinline__ void mma_tf32(float* d, const uint32_t* a,
                                         const uint32_t* b) {
    asm volatile(
        "mma.sync.aligned.m16n8k8.row.col.f32.tf32.tf32.f32 "
        "{%0,%1,%2,%3}, {%4,%5,%6,%7}, {%8,%9}, {%0,%1,%2,%3};"
        : "+f"(d[0]), "+f"(d[1]), "+f"(d[2]), "+f"(d[3])
        : "r"(a[0]), "r"(a[1]), "r"(a[2]), "r"(a[3]), "r"(b[0]), "r"(b[1]));
}

// ---------------------------------------------------------------------------
// pre-round v to tf32 (one float4 per thread)
// ---------------------------------------------------------------------------
__global__ __launch_bounds__(256) void cvt_kernel(const float* __restrict__ v) {
    int i = (blockIdx.x * 256 + threadIdx.x) * 4;
    float4 x = *(const float4*)(v + i);
    float4 r = make_float4(tf32_rn(x.x), tf32_rn(x.y), tf32_rn(x.z), tf32_rn(x.w));
    *(float4*)(vt_buf + i) = r;
}

// ---------------------------------------------------------------------------
// pbv[n,j,h,d] = sum_l w[h,|l-j|] * v[n,l,h,d] as per-head Toeplitz GEMM.
// grid (16 j-tiles, 2 c-halves, 12 heads); CTA 128x128, 8 warps of 64x32.
// Double-buffered smem, cp.async B staging, 1 sync per chunk.
// ---------------------------------------------------------------------------
__global__ __launch_bounds__(THREADS, 2) void pbv_mma(const float* __restrict__ w,
                                                      float* __restrict__ out) {
    __shared__ float wsf[SS];                  // 8 KB tf32-rounded w row
    extern __shared__ uint32_t dyn[];          // As0 | As1 | Bs0 | Bs1

    const int t   = threadIdx.x;
    const int wid = t >> 5, lane = t & 31;
    const int g   = lane >> 2, t4 = lane & 3;
    const int wm  = wid >> 2;                  // 0..1 -> 64-row slab
    const int wn  = wid & 3;                   // 0..3 -> 32-col slab

    const int jt = blockIdx.x, ch = blockIdx.y, h = blockIdx.z;
    const int j0 = jt * TM;
    const int c0 = ch * TN;

    {
        const float* wrow = w + (size_t)h * SS;
        for (int i = t; i < SS; i += THREADS) wsf[i] = tf32_rn(wrow[i]);
    }
    __syncthreads();

    const float* vtb = vt_buf + h * ND;        // + (n*SS + l)*ROWSTRIDE + d
    const uint32_t sbB0 = smem_u32(dyn + 2 * TILEU);
    const uint32_t sbB1 = smem_u32(dyn + 3 * TILEU);

    // ---- stage chunk `c` into buffer c&1
    auto stage = [&](int c) {
        const int k0 = c * KC;
        uint32_t* Ab = dyn + (c & 1) * TILEU;
#pragma unroll
        for (int i = 0; i < 16; i++) {
            int e = t + i * THREADS;           // 0..4095
            int k = e >> 7, j = e & 127;
            int l = k0 + k;
            int delta = l - (j0 + j);
            int ad = delta < 0 ? -delta : delta;
            float val = (l >= 1 && l <= SEQ) ? wsf[ad] : 0.f;
            Ab[k * ASTRIDE + j] = __float_as_uint(val);
        }
        const uint32_t Bbase = (c & 1) ? sbB1 : sbB0;
#pragma unroll
        for (int q = 0; q < 4; q++) {
            int fi = t + q * THREADS;          // 16B slot 0..1023
            int k  = fi >> 5;
            int c4 = fi & 31;
            int cc = c0 + c4 * 4;
            int n  = cc >> 6, d = cc & 63;
            const float* src = vtb + ((size_t)n * SS + (k0 + k)) * ROWSTRIDE + d;
            cp_async16(Bbase + (uint32_t)(k * ASTRIDE + c4 * 4) * 4, src);
        }
        CP_COMMIT();
    };

    float acc[4][4][4];
#pragma unroll
    for (int mi = 0; mi < 4; mi++)
#pragma unroll
        for (int ni = 0; ni < 4; ni++)
#pragma unroll
            for (int r = 0; r < 4; r++) acc[mi][ni][r] = 0.f;

    stage(0);

    for (int c = 0; c < NCHUNK; c++) {
        CP_WAIT0();              // B(c) landed (B(c+1) not yet issued)
        __syncthreads();         // A(c) visible; buf[(c+1)&1] free (read in c-1)

        if (c + 1 < NCHUNK) stage(c + 1);

        const uint32_t* Ab = dyn + (c & 1) * TILEU;
        const uint32_t* Bb = dyn + (2 + (c & 1)) * TILEU;

#pragma unroll
        for (int ks = 0; ks < 4; ks++) {
            const int kb = ks * 8;
            uint32_t a[4][4], b[4][2];
#pragma unroll
            for (int mi = 0; mi < 4; mi++) {
                const int j = wm * 64 + mi * 16 + g;
                a[mi][0] = Ab[(kb + t4) * ASTRIDE + j];
                a[mi][1] = Ab[(kb + t4) * ASTRIDE + j + 8];
                a[mi][2] = Ab[(kb + t4 + 4) * ASTRIDE + j];
                a[mi][3] = Ab[(kb + t4 + 4) * ASTRIDE + j + 8];
            }
#pragma unroll
            for (int ni = 0; ni < 4; ni++) {
                const int cc = wn * 32 + ni * 8 + g;
                b[ni][0] = Bb[(kb + t4) * ASTRIDE + cc];
                b[ni][1] = Bb[(kb + t4 + 4) * ASTRIDE + cc];
            }
#pragma unroll
            for (int mi = 0; mi < 4; mi++)
#pragma unroll
                for (int ni = 0; ni < 4; ni++)
                    mma_tf32(acc[mi][ni], a[mi], b[ni]);
        }
    }

    // ---- epilogue: acc -> out[n, j, h, d]
#pragma unroll
    for (int mi = 0; mi < 4; mi++) {
        const int r0 = j0 + wm * 64 + mi * 16 + g;
#pragma unroll
        for (int ni = 0; ni < 4; ni++) {
            const int cc = c0 + wn * 32 + ni * 8 + 2 * t4;
            const int n = cc >> 6, d = cc & 63;
            float* o = out + (((size_t)n * SS) * NH + h) * ND + d;
            if (r0 >= 1 && r0 <= SEQ) {
                float2 s = make_float2(acc[mi][ni][0], acc[mi][ni][1]);
                *(float2*)(o + (size_t)r0 * NH * ND) = s;
            }
            const int r1 = r0 + 8;
            if (r1 >= 1 && r1 <= SEQ) {
                float2 s = make_float2(acc[mi][ni][2], acc[mi][ni][3]);
                *(float2*)(o + (size_t)r1 * NH * ND) = s;
            }
        }
    }
}

// ---------------------------------------------------------------------------
// z_pb[l,h] = P[l-1] + P[SEQ-l] - w[h,0]; Hillis-Steele scan per head
// ---------------------------------------------------------------------------
__global__ __launch_bounds__(1024) void z_kernel(const float* __restrict__ w,
                                                 float* __restrict__ outz) {
    const int h = blockIdx.x;
    __shared__ float buf[2][SS];
    for (int i = threadIdx.x; i < SS; i += 1024)
        buf[0][i] = (i < SEQ) ? w[(size_t)h * SS + i] : 0.f;
    __syncthreads();
    int src = 0;
    for (int off = 1; off < SS; off <<= 1) {
        for (int i = threadIdx.x; i < SS; i += 1024) {
            float val = buf[src][i];
            if (i >= off) val += buf[src][i - off];
            buf[src ^ 1][i] = val;
        }
        src ^= 1;
        __syncthreads();
    }
    const float w0 = buf[src][0];
    for (int l = threadIdx.x; l < SS; l += 1024) {
        float zv = 0.f;
        if (l >= 1 && l <= SEQ)
            zv = buf[src][l - 1] + buf[src][SEQ - l] - w0;
        outz[(size_t)l * NH + h] = zv;
    }
}

// zero pbv border rows j=0 and j=2047 (d_out poisoned)
__global__ void border_kernel(float* __restrict__ out) {
    int g = blockIdx.x * blockDim.x + threadIdx.x;
    if (g >= 8 * NH * ND) return;
    int seg = g / (NH * ND);
    int off = g % (NH * ND);
    int n = seg >> 1;
    int j = (seg & 1) ? (SS - 1) : 0;
    out[((size_t)(n * SS + j) * NH * ND) + off] = 0.f;
}

// ---------------------------------------------------------------------------
extern "C" void kernel_launch(void* const* d_in, const int* in_sizes, int n_in,
                              void* d_out, int out_size) {
    const float* a0 = (const float*)d_in[0];
    const float* a1 = (const float*)d_in[1];
    const float* v = a0;
    const float* w = a1;
    if (n_in >= 2 && in_sizes[0] < in_sizes[1]) { v = a1; w = a0; }

    float* out  = (float*)d_out;
    float* outz = out + (size_t)SB * SS * NH * ND;

    static int configured = 0;
    if (!configured) {
        cudaFuncSetAttribute(pbv_mma, cudaFuncAttributeMaxDynamicSharedMemorySize,
                             DYN_BYTES);
        configured = 1;
    }

    cvt_kernel<<<NV / (256 * 4), 256>>>(v);
    dim3 grid(SS / TM, 2, NH);               // 16 x 2 x 12 = 384 CTAs
    pbv_mma<<<grid, THREADS, DYN_BYTES>>>(w, out);
    z_kernel<<<NH, 1024>>>(w, outz);
    border_kernel<<<6, 1024>>>(out);
}

// round 6
// speedup vs baseline: 6.6878x; 1.6304x over previous
#include <cuda_runtime.h>
#include <cuda_fp16.h>
#include <cstdint>

// ---------------- problem constants ----------------
#define SB   4
#define SS   2048
#define SEQ  2046
#define NH   12
#define ND   64
#define ROWSTRIDE (NH*ND)        // 768 elems between consecutive l in v
#define NV   (SB*SS*NH*ND)       // 6291456 elements of v

// ---------------- GEMM tiling ----------------
#define TM    128                // j rows per CTA
#define TN    128                // c cols per CTA (2 n * 64 d)
#define KC    32                 // l per chunk
#define NCHUNK (SS / KC)         // 64
#define THREADS 256

#define A_STR  40                // halves per j row (32 k + 8 pad) -> 20 words
#define B_STR  136               // halves per k row (128 c + 8 pad) -> 68 words
#define A_BYTES (TM * A_STR * 2)         // 10240
#define B_BYTES (KC * B_STR * 2)         // 8704
#define DYN_BYTES (2*A_BYTES + 2*B_BYTES) // 37888

// fp16 copy of v (device-global scratch)
__device__ __half vt_h[NV];

__device__ __forceinline__ uint32_t smem_u32(const void* p) {
    uint32_t a;
    asm("{ .reg .u64 t; cvta.to.shared.u64 t, %1; cvt.u32.u64 %0, t; }"
        : "=r"(a) : "l"(p));
    return a;
}
__device__ __forceinline__ void cp_async16(uint32_t dst, const void* src) {
    asm volatile("cp.async.ca.shared.global [%0], [%1], 16;"
                 :: "r"(dst), "l"(src) : "memory");
}
#define CP_COMMIT() asm volatile("cp.async.commit_group;" ::: "memory")
#define CP_WAIT0()  asm volatile("cp.async.wait_group 0;" ::: "memory")

__device__ __forceinline__ void ldsm_x4(uint32_t* r, uint32_t addr) {
    asm volatile("ldmatrix.sync.aligned.m8n8.x4.shared.b16 {%0,%1,%2,%3}, [%4];"
                 : "=r"(r[0]), "=r"(r[1]), "=r"(r[2]), "=r"(r[3]) : "r"(addr));
}
__device__ __forceinline__ void ldsm_x4_t(uint32_t* r, uint32_t addr) {
    asm volatile("ldmatrix.sync.aligned.m8n8.x4.trans.shared.b16 {%0,%1,%2,%3}, [%4];"
                 : "=r"(r[0]), "=r"(r[1]), "=r"(r[2]), "=r"(r[3]) : "r"(addr));
}
__device__ __forceinline__ void mma_f16(float* d, const uint32_t* a,
                                        const uint32_t* b) {
    asm volatile(
        "mma.sync.aligned.m16n8k16.row.col.f32.f16.f16.f32 "
        "{%0,%1,%2,%3}, {%4,%5,%6,%7}, {%8,%9}, {%0,%1,%2,%3};"
        : "+f"(d[0]), "+f"(d[1]), "+f"(d[2]), "+f"(d[3])
        : "r"(a[0]), "r"(a[1]), "r"(a[2]), "r"(a[3]), "r"(b[0]), "r"(b[1]));
}

// ---------------------------------------------------------------------------
// convert v (fp32) -> vt_h (fp16); 8 elements per thread
// ---------------------------------------------------------------------------
__global__ __launch_bounds__(256) void cvt_kernel(const float* __restrict__ v) {
    int i = (blockIdx.x * 256 + threadIdx.x) * 8;
    float4 x0 = *(const float4*)(v + i);
    float4 x1 = *(const float4*)(v + i + 4);
    __half2 h[4];
    h[0] = __floats2half2_rn(x0.x, x0.y);
    h[1] = __floats2half2_rn(x0.z, x0.w);
    h[2] = __floats2half2_rn(x1.x, x1.y);
    h[3] = __floats2half2_rn(x1.z, x1.w);
    *(uint4*)(vt_h + i) = *(uint4*)h;
}

// ---------------------------------------------------------------------------
// pbv[n,j,h,d] = sum_l w[h,|l-j|] * v[n,l,h,d] as per-head Toeplitz GEMM.
// grid (16 j-tiles, 2 c-halves, 12 heads); CTA 128x128 fp16 MMA, 8 warps 64x32.
// ---------------------------------------------------------------------------
__global__ __launch_bounds__(THREADS, 2) void pbv_mma(const float* __restrict__ w,
                                                      float* __restrict__ out) {
    __shared__ __half wsh[SS];                  // 4 KB fp16 w row
    extern __shared__ char dyn[];               // A0 | A1 | B0 | B1

    const int t    = threadIdx.x;
    const int wid  = t >> 5, lane = t & 31;
    const int g    = lane >> 2, t4 = lane & 3;
    const int wm   = wid >> 2;                  // 0..1 -> 64-row slab
    const int wn   = wid & 3;                   // 0..3 -> 32-col slab
    const int l15  = lane & 15, lhi = lane >> 4; // ldmatrix lane split

    const int jt = blockIdx.x, ch = blockIdx.y, h = blockIdx.z;
    const int j0 = jt * TM;
    const int c0 = ch * TN;

    {
        const float* wrow = w + (size_t)h * SS;
        for (int i = t; i < SS; i += THREADS) wsh[i] = __float2half_rn(wrow[i]);
    }
    __syncthreads();

    const __half* vtb = vt_h + h * ND;          // + (n*SS + l)*ROWSTRIDE + d
    const uint32_t sb = smem_u32(dyn);

    // ---- stage chunk `c` into buffer c&1
    auto stage = [&](int c) {
        const int k0 = c * KC;
        __half2* Ab = (__half2*)(dyn + (c & 1) * A_BYTES);
#pragma unroll
        for (int i = 0; i < 8; i++) {
            int e  = t + i * THREADS;           // 0..2047
            int kp = e & 15, j = e >> 4;
            int jg = j0 + j;
            int l0 = k0 + 2 * kp;
            int d0 = l0 - jg;     int a0i = d0 < 0 ? -d0 : d0;
            int d1 = d0 + 1;      int a1i = d1 < 0 ? -d1 : d1;
            __half v0 = (l0 >= 1     && l0     <= SEQ) ? wsh[a0i] : __half(0.f);
            __half v1 = (l0 + 1 >= 1 && l0 + 1 <= SEQ) ? wsh[a1i] : __half(0.f);
            Ab[j * (A_STR / 2) + kp] = __halves2half2(v0, v1);
        }
        const uint32_t Bbase = sb + 2 * A_BYTES + (c & 1) * B_BYTES;
#pragma unroll
        for (int q = 0; q < 2; q++) {
            int fi = t + q * THREADS;           // 0..511, 16B slots
            int k  = fi >> 4, c8 = fi & 15;
            int cc = c0 + c8 * 8;
            int n  = cc >> 6, d = cc & 63;
            const __half* src = vtb + ((size_t)n * SS + (k0 + k)) * ROWSTRIDE + d;
            cp_async16(Bbase + (uint32_t)(k * B_STR + c8 * 8) * 2, src);
        }
        CP_COMMIT();
    };

    float acc[4][4][4];
#pragma unroll
    for (int mi = 0; mi < 4; mi++)
#pragma unroll
        for (int ni = 0; ni < 4; ni++)
#pragma unroll
            for (int r = 0; r < 4; r++) acc[mi][ni][r] = 0.f;

    // per-lane ldmatrix address components (element offsets within tile)
    const uint32_t aRow = (uint32_t)(wm * 64 + l15);       // + mi*16
    const uint32_t aKof = (uint32_t)(lhi * 8);             // + ks*16
    const uint32_t bRow = (uint32_t)l15;                   // + ks*16
    const uint32_t bCol = (uint32_t)(wn * 32 + lhi * 8);   // + ni2*16

    stage(0);

    for (int c = 0; c < NCHUNK; c++) {
        CP_WAIT0();
        __syncthreads();
        if (c + 1 < NCHUNK) stage(c + 1);

        const uint32_t Ao = sb + (c & 1) * A_BYTES;
        const uint32_t Bo = sb + 2 * A_BYTES + (c & 1) * B_BYTES;

#pragma unroll
        for (int ks = 0; ks < 2; ks++) {
            uint32_t a[4][4], b[4][2];
#pragma unroll
            for (int mi = 0; mi < 4; mi++)
                ldsm_x4(a[mi], Ao + ((aRow + mi * 16) * A_STR + aKof + ks * 16) * 2);
#pragma unroll
            for (int ni2 = 0; ni2 < 2; ni2++) {
                uint32_t r[4];
                ldsm_x4_t(r, Bo + ((bRow + ks * 16) * B_STR + bCol + ni2 * 16) * 2);
                b[2 * ni2][0] = r[0];  b[2 * ni2][1] = r[1];
                b[2 * ni2 + 1][0] = r[2];  b[2 * ni2 + 1][1] = r[3];
            }
#pragma unroll
            for (int mi = 0; mi < 4; mi++)
#pragma unroll
                for (int ni = 0; ni < 4; ni++)
                    mma_f16(acc[mi][ni], a[mi], b[ni]);
        }
    }

    // ---- epilogue: acc -> out[n, j, h, d]
#pragma unroll
    for (int mi = 0; mi < 4; mi++) {
        const int r0 = j0 + wm * 64 + mi * 16 + g;
#pragma unroll
        for (int ni = 0; ni < 4; ni++) {
            const int cc = c0 + wn * 32 + ni * 8 + 2 * t4;
            const int n = cc >> 6, d = cc & 63;
            float* o = out + (((size_t)n * SS) * NH + h) * ND + d;
            if (r0 >= 1 && r0 <= SEQ) {
                float2 s = make_float2(acc[mi][ni][0], acc[mi][ni][1]);
                *(float2*)(o + (size_t)r0 * NH * ND) = s;
            }
            const int r1 = r0 + 8;
            if (r1 >= 1 && r1 <= SEQ) {
                float2 s = make_float2(acc[mi][ni][2], acc[mi][ni][3]);
                *(float2*)(o + (size_t)r1 * NH * ND) = s;
            }
        }
    }
}

// ---------------------------------------------------------------------------
// blocks 0..11: z_pb scan per head; blocks 12..17: zero pbv border rows
// ---------------------------------------------------------------------------
__global__ __launch_bounds__(1024) void zb_kernel(const float* __restrict__ w,
                                                  float* __restrict__ outz,
                                                  float* __restrict__ out) {
    const int b = blockIdx.x;
    if (b >= NH) {   // border: 6 blocks x 1024 cover 8 segs x 768
        int gidx = (b - NH) * 1024 + threadIdx.x;
        if (gidx < 8 * NH * ND) {
            int seg = gidx / (NH * ND);
            int off = gidx % (NH * ND);
            int n = seg >> 1;
            int j = (seg & 1) ? (SS - 1) : 0;
            out[((size_t)(n * SS + j) * NH * ND) + off] = 0.f;
        }
        return;
    }
    const int h = b;
    __shared__ float buf[2][SS];
    for (int i = threadIdx.x; i < SS; i += 1024)
        buf[0][i] = (i < SEQ) ? w[(size_t)h * SS + i] : 0.f;
    __syncthreads();
    int src = 0;
    for (int off = 1; off < SS; off <<= 1) {
        for (int i = threadIdx.x; i < SS; i += 1024) {
            float val = buf[src][i];
            if (i >= off) val += buf[src][i - off];
            buf[src ^ 1][i] = val;
        }
        src ^= 1;
        __syncthreads();
    }
    const float w0 = buf[src][0];
    for (int l = threadIdx.x; l < SS; l += 1024) {
        float zv = 0.f;
        if (l >= 1 && l <= SEQ)
            zv = buf[src][l - 1] + buf[src][SEQ - l] - w0;
        outz[(size_t)l * NH + h] = zv;
    }
}

// ---------------------------------------------------------------------------
extern "C" void kernel_launch(void* const* d_in, const int* in_sizes, int n_in,
                              void* d_out, int out_size) {
    const float* a0 = (const float*)d_in[0];
    const float* a1 = (const float*)d_in[1];
    const float* v = a0;
    const float* w = a1;
    if (n_in >= 2 && in_sizes[0] < in_sizes[1]) { v = a1; w = a0; }

    float* out  = (float*)d_out;
    float* outz = out + (size_t)SB * SS * NH * ND;

    static int configured = 0;
    if (!configured) {
        cudaFuncSetAttribute(pbv_mma, cudaFuncAttributeMaxDynamicSharedMemorySize,
                             DYN_BYTES);
        configured = 1;
    }

    cvt_kernel<<<NV / (256 * 8), 256>>>(v);
    dim3 grid(SS / TM, 2, NH);               // 16 x 2 x 12 = 384 CTAs
    pbv_mma<<<grid, THREADS, DYN_BYTES>>>(w, out);
    zb_kernel<<<NH + 6, 1024>>>(w, outz, out);
}

// round 7
// speedup vs baseline: 7.0730x; 1.0576x over previous
#include <cuda_runtime.h>
#include <cuda_fp16.h>
#include <cstdint>

// ---------------- problem constants ----------------
#define SB   4
#define SS   2048
#define SEQ  2046
#define NH   12
#define ND   64
#define ROWSTRIDE (NH*ND)        // 768 elems between consecutive l in v
#define NV   (SB*SS*NH*ND)       // 6291456 elements of v

// ---------------- GEMM tiling ----------------
#define TM    64                 // j rows per CTA
#define TN    128                // c cols per CTA (2 n * 64 d)
#define KC    32                 // l per chunk
#define NCHUNK (SS / KC)         // 64
#define THREADS 256

#define A_STR  40                // halves per j row (32 k + 8 pad)
#define B_STR  136               // halves per k row (128 c + 8 pad)
#define A_BYTES (TM * A_STR * 2)          // 5120
#define B_BYTES (KC * B_STR * 2)          // 8704
#define DYN_BYTES (2*A_BYTES + 2*B_BYTES) // 27648

// fp16 copy of v (device-global scratch)
__device__ __half vt_h[NV];

__device__ __forceinline__ uint32_t smem_u32(const void* p) {
    uint32_t a;
    asm("{ .reg .u64 t; cvta.to.shared.u64 t, %1; cvt.u32.u64 %0, t; }"
        : "=r"(a) : "l"(p));
    return a;
}
__device__ __forceinline__ void cp_async16(uint32_t dst, const void* src) {
    asm volatile("cp.async.ca.shared.global [%0], [%1], 16;"
                 :: "r"(dst), "l"(src) : "memory");
}
#define CP_COMMIT() asm volatile("cp.async.commit_group;" ::: "memory")
#define CP_WAIT0()  asm volatile("cp.async.wait_group 0;" ::: "memory")

__device__ __forceinline__ void ldsm_x4(uint32_t* r, uint32_t addr) {
    asm volatile("ldmatrix.sync.aligned.m8n8.x4.shared.b16 {%0,%1,%2,%3}, [%4];"
                 : "=r"(r[0]), "=r"(r[1]), "=r"(r[2]), "=r"(r[3]) : "r"(addr));
}
__device__ __forceinline__ void ldsm_x4_t(uint32_t* r, uint32_t addr) {
    asm volatile("ldmatrix.sync.aligned.m8n8.x4.trans.shared.b16 {%0,%1,%2,%3}, [%4];"
                 : "=r"(r[0]), "=r"(r[1]), "=r"(r[2]), "=r"(r[3]) : "r"(addr));
}
__device__ __forceinline__ void mma_f16(float* d, const uint32_t* a,
                                        const uint32_t* b) {
    asm volatile(
        "mma.sync.aligned.m16n8k16.row.col.f32.f16.f16.f32 "
        "{%0,%1,%2,%3}, {%4,%5,%6,%7}, {%8,%9}, {%0,%1,%2,%3};"
        : "+f"(d[0]), "+f"(d[1]), "+f"(d[2]), "+f"(d[3])
        : "r"(a[0]), "r"(a[1]), "r"(a[2]), "r"(a[3]), "r"(b[0]), "r"(b[1]));
}

// ---------------------------------------------------------------------------
// convert v (fp32) -> vt_h (fp16); 8 elements per thread
// ---------------------------------------------------------------------------
__global__ __launch_bounds__(256) void cvt_kernel(const float* __restrict__ v) {
    int i = (blockIdx.x * 256 + threadIdx.x) * 8;
    float4 x0 = *(const float4*)(v + i);
    float4 x1 = *(const float4*)(v + i + 4);
    __half2 h[4];
    h[0] = __floats2half2_rn(x0.x, x0.y);
    h[1] = __floats2half2_rn(x0.z, x0.w);
    h[2] = __floats2half2_rn(x1.x, x1.y);
    h[3] = __floats2half2_rn(x1.z, x1.w);
    *(uint4*)(vt_h + i) = *(uint4*)h;
}

// ---------------------------------------------------------------------------
// pbv[n,j,h,d] = sum_l w[h,|l-j|] * v[n,l,h,d] as per-head Toeplitz GEMM.
// grid (32 j-tiles, 2 c-halves, 12 heads); CTA 64x128 fp16 MMA, 8 warps 32x32.
// Target 3 CTAs/SM to kill wave quantization.
// ---------------------------------------------------------------------------
__global__ __launch_bounds__(THREADS, 3) void pbv_mma(const float* __restrict__ w,
                                                      float* __restrict__ out) {
    __shared__ __half wsh[SS];                  // 4 KB fp16 w row
    extern __shared__ char dyn[];               // A0 | A1 | B0 | B1

    const int t    = threadIdx.x;
    const int wid  = t >> 5, lane = t & 31;
    const int g    = lane >> 2, t4 = lane & 3;
    const int wm   = wid >> 2;                  // 0..1 -> 32-row slab
    const int wn   = wid & 3;                   // 0..3 -> 32-col slab
    const int l15  = lane & 15, lhi = lane >> 4;

    const int jt = blockIdx.x, ch = blockIdx.y, h = blockIdx.z;
    const int j0 = jt * TM;
    const int c0 = ch * TN;

    {
        const float* wrow = w + (size_t)h * SS;
        for (int i = t; i < SS; i += THREADS) wsh[i] = __float2half_rn(wrow[i]);
    }
    __syncthreads();

    const __half* vtb = vt_h + h * ND;          // + (n*SS + l)*ROWSTRIDE + d
    const uint32_t sb = smem_u32(dyn);

    // ---- stage chunk `c` into buffer c&1
    auto stage = [&](int c) {
        const int k0 = c * KC;
        __half2* Ab = (__half2*)(dyn + (c & 1) * A_BYTES);
#pragma unroll
        for (int i = 0; i < 4; i++) {
            int e  = t + i * THREADS;           // 0..1023
            int kp = e & 15, j = e >> 4;        // j 0..63
            int jg = j0 + j;
            int l0 = k0 + 2 * kp;
            int d0 = l0 - jg;     int a0i = d0 < 0 ? -d0 : d0;
            int d1 = d0 + 1;      int a1i = d1 < 0 ? -d1 : d1;
            __half v0 = (l0 >= 1     && l0     <= SEQ) ? wsh[a0i] : __half(0.f);
            __half v1 = (l0 + 1 >= 1 && l0 + 1 <= SEQ) ? wsh[a1i] : __half(0.f);
            Ab[j * (A_STR / 2) + kp] = __halves2half2(v0, v1);
        }
        const uint32_t Bbase = sb + 2 * A_BYTES + (c & 1) * B_BYTES;
#pragma unroll
        for (int q = 0; q < 2; q++) {
            int fi = t + q * THREADS;           // 0..511, 16B slots
            int k  = fi >> 4, c8 = fi & 15;
            int cc = c0 + c8 * 8;
            int n  = cc >> 6, d = cc & 63;
            const __half* src = vtb + ((size_t)n * SS + (k0 + k)) * ROWSTRIDE + d;
            cp_async16(Bbase + (uint32_t)(k * B_STR + c8 * 8) * 2, src);
        }
        CP_COMMIT();
    };

    float acc[2][4][4];
#pragma unroll
    for (int mi = 0; mi < 2; mi++)
#pragma unroll
        for (int ni = 0; ni < 4; ni++)
#pragma unroll
            for (int r = 0; r < 4; r++) acc[mi][ni][r] = 0.f;

    const uint32_t aRow = (uint32_t)(wm * 32 + l15);       // + mi*16
    const uint32_t aKof = (uint32_t)(lhi * 8);             // + ks*16
    const uint32_t bRow = (uint32_t)l15;                   // + ks*16
    const uint32_t bCol = (uint32_t)(wn * 32 + lhi * 8);   // + ni2*16

    stage(0);

    for (int c = 0; c < NCHUNK; c++) {
        CP_WAIT0();
        __syncthreads();
        if (c + 1 < NCHUNK) stage(c + 1);

        const uint32_t Ao = sb + (c & 1) * A_BYTES;
        const uint32_t Bo = sb + 2 * A_BYTES + (c & 1) * B_BYTES;

#pragma unroll
        for (int ks = 0; ks < 2; ks++) {
            uint32_t a[2][4], b[4][2];
#pragma unroll
            for (int mi = 0; mi < 2; mi++)
                ldsm_x4(a[mi], Ao + ((aRow + mi * 16) * A_STR + aKof + ks * 16) * 2);
#pragma unroll
            for (int ni2 = 0; ni2 < 2; ni2++) {
                uint32_t r[4];
                ldsm_x4_t(r, Bo + ((bRow + ks * 16) * B_STR + bCol + ni2 * 16) * 2);
                b[2 * ni2][0] = r[0];      b[2 * ni2][1] = r[1];
                b[2 * ni2 + 1][0] = r[2];  b[2 * ni2 + 1][1] = r[3];
            }
#pragma unroll
            for (int mi = 0; mi < 2; mi++)
#pragma unroll
                for (int ni = 0; ni < 4; ni++)
                    mma_f16(acc[mi][ni], a[mi], b[ni]);
        }
    }

    // ---- epilogue: acc -> out[n, j, h, d]
#pragma unroll
    for (int mi = 0; mi < 2; mi++) {
        const int r0 = j0 + wm * 32 + mi * 16 + g;
#pragma unroll
        for (int ni = 0; ni < 4; ni++) {
            const int cc = c0 + wn * 32 + ni * 8 + 2 * t4;
            const int n = cc >> 6, d = cc & 63;
            float* o = out + (((size_t)n * SS) * NH + h) * ND + d;
            if (r0 >= 1 && r0 <= SEQ) {
                float2 s = make_float2(acc[mi][ni][0], acc[mi][ni][1]);
                *(float2*)(o + (size_t)r0 * NH * ND) = s;
            }
            const int r1 = r0 + 8;
            if (r1 >= 1 && r1 <= SEQ) {
                float2 s = make_float2(acc[mi][ni][2], acc[mi][ni][3]);
                *(float2*)(o + (size_t)r1 * NH * ND) = s;
            }
        }
    }
}

// ---------------------------------------------------------------------------
// blocks 0..11: z_pb scan per head; blocks 12..17: zero pbv border rows
// ---------------------------------------------------------------------------
__global__ __launch_bounds__(1024) void zb_kernel(const float* __restrict__ w,
                                                  float* __restrict__ outz,
                                                  float* __restrict__ out) {
    const int b = blockIdx.x;
    if (b >= NH) {   // border: 6 blocks x 1024 cover 8 segs x 768
        int gidx = (b - NH) * 1024 + threadIdx.x;
        if (gidx < 8 * NH * ND) {
            int seg = gidx / (NH * ND);
            int off = gidx % (NH * ND);
            int n = seg >> 1;
            int j = (seg & 1) ? (SS - 1) : 0;
            out[((size_t)(n * SS + j) * NH * ND) + off] = 0.f;
        }
        return;
    }
    const int h = b;
    __shared__ float buf[2][SS];
    for (int i = threadIdx.x; i < SS; i += 1024)
        buf[0][i] = (i < SEQ) ? w[(size_t)h * SS + i] : 0.f;
    __syncthreads();
    int src = 0;
    for (int off = 1; off < SS; off <<= 1) {
        for (int i = threadIdx.x; i < SS; i += 1024) {
            float val = buf[src][i];
            if (i >= off) val += buf[src][i - off];
            buf[src ^ 1][i] = val;
        }
        src ^= 1;
        __syncthreads();
    }
    const float w0 = buf[src][0];
    for (int l = threadIdx.x; l < SS; l += 1024) {
        float zv = 0.f;
        if (l >= 1 && l <= SEQ)
            zv = buf[src][l - 1] + buf[src][SEQ - l] - w0;
        outz[(size_t)l * NH + h] = zv;
    }
}

// ---------------------------------------------------------------------------
extern "C" void kernel_launch(void* const* d_in, const int* in_sizes, int n_in,
                              void* d_out, int out_size) {
    const float* a0 = (const float*)d_in[0];
    const float* a1 = (const float*)d_in[1];
    const float* v = a0;
    const float* w = a1;
    if (n_in >= 2 && in_sizes[0] < in_sizes[1]) { v = a1; w = a0; }

    float* out  = (float*)d_out;
    float* outz = out + (size_t)SB * SS * NH * ND;

    static int configured = 0;
    if (!configured) {
        cudaFuncSetAttribute(pbv_mma, cudaFuncAttributeMaxDynamicSharedMemorySize,
                             DYN_BYTES);
        configured = 1;
    }

    cvt_kernel<<<NV / (256 * 8), 256>>>(v);
    dim3 grid(SS / TM, 2, NH);               // 32 x 2 x 12 = 768 CTAs
    pbv_mma<<<grid, THREADS, DYN_BYTES>>>(w, out);
    zb_kernel<<<NH + 6, 1024>>>(w, outz, out);
}